// round 6
// baseline (speedup 1.0000x reference)
#include <cuda_runtime.h>
#include <math.h>

#define MAXD 2048
#define TILE 64
#define NTMAX (MAXD / TILE)
#define ETA 0.005f

// Disjoint partials: g_partM[p][j] = contribution of "other tile" p to column j.
// Every slot is written exactly once per launch -> no zeroing, no atomics.
__device__ float g_partM[NTMAX][MAXD];   // 256 KB
__device__ float g_m[MAXD];              // reduced + scaled by 1/D
__device__ unsigned int g_ctr = 0;       // arrival counter (reset by last block)

// ---------------------------------------------------------------------------
// Kernel 1: symmetric tile-pair reduction + fused final reduce (last block).
// Block handles unordered {I,J}, I <= J; reads tiles A = x[I,J], B = x[J,I]
// once, coalesced. P[u,v] = A[u][v] * B[v][u].
//   pass 1: col-sums of P -> g_partM[I][J*64+v]
//   pass 2: row-sums of P -> g_partM[J][I*64+u]
// Diagonal (I==J): pass 1 only, with B := A.
// ---------------------------------------------------------------------------
__global__ void __launch_bounds__(256) hebb_tile_kernel(
    const float* __restrict__ x, int D, int NT, float invD)
{
    __shared__ float A[TILE][TILE + 1];
    __shared__ float B[TILE][TILE + 1];
    __shared__ float redM[4][TILE];
    __shared__ unsigned int s_rank;

    // Invert triangular index: bid -> (I, J), I <= J, row-major upper.
    const int t = blockIdx.x;
    const float fN = 2.0f * (float)NT + 1.0f;
    int I = (int)((fN - sqrtf(fN * fN - 8.0f * (float)t)) * 0.5f);
    #define TRI_BASE(i) ((i) * NT - ((i) * ((i) - 1)) / 2)
    while (I > 0 && TRI_BASE(I) > t) I--;
    while (TRI_BASE(I + 1) <= t) I++;
    const int J = I + (t - TRI_BASE(I));
    #undef TRI_BASE

    const int tid = threadIdx.x;
    const int r   = tid >> 2;          // 0..63  (row within tile)
    const int cg  = (tid & 3) << 4;    // 0,16,32,48 (col group)
    const bool diag = (I == J);

    // Load A (coalesced: warp covers 8 rows x 64 consecutive floats).
    {
        const float* ap = x + (size_t)(I * TILE + r) * D + J * TILE + cg;
        #pragma unroll
        for (int k = 0; k < 16; k += 4) {
            float4 v = *reinterpret_cast<const float4*>(ap + k);
            A[r][cg + k + 0] = v.x; A[r][cg + k + 1] = v.y;
            A[r][cg + k + 2] = v.z; A[r][cg + k + 3] = v.w;
        }
    }
    if (!diag) {
        const float* bp = x + (size_t)(J * TILE + r) * D + I * TILE + cg;
        #pragma unroll
        for (int k = 0; k < 16; k += 4) {
            float4 v = *reinterpret_cast<const float4*>(bp + k);
            B[r][cg + k + 0] = v.x; B[r][cg + k + 1] = v.y;
            B[r][cg + k + 2] = v.z; B[r][cg + k + 3] = v.w;
        }
    }
    __syncthreads();

    float (*Bt)[TILE + 1] = diag ? A : B;

    // Pass 1: per-column v; group g sums rows u0..u0+15.
    {
        const int v  = tid & 63;
        const int g  = tid >> 6;
        const int u0 = g << 4;
        float am = 0.0f;
        #pragma unroll
        for (int k = 0; k < 16; k++) {
            const int u = u0 + k;
            am += A[u][v] * Bt[v][u];   // stride-1 / stride-65: conflict-free
        }
        redM[g][v] = am;
    }
    __syncthreads();
    if (tid < 64)
        g_partM[I][J * TILE + tid] =
            redM[0][tid] + redM[1][tid] + redM[2][tid] + redM[3][tid];

    if (!diag) {
        __syncthreads();
        // Pass 2: per-row u; group g sums cols v0..v0+15.
        {
            const int u  = tid & 63;
            const int g  = tid >> 6;
            const int v0 = g << 4;
            float am = 0.0f;
            #pragma unroll
            for (int k = 0; k < 16; k++) {
                const int v = v0 + k;
                am += A[u][v] * B[v][u];
            }
            redM[g][u] = am;
        }
        __syncthreads();
        if (tid < 64)
            g_partM[J][I * TILE + tid] =
                redM[0][tid] + redM[1][tid] + redM[2][tid] + redM[3][tid];
    }

    // ---- last-block fused reduction of partials into g_m ----
    __threadfence();                    // publish this block's partials
    __syncthreads();
    if (tid == 0) s_rank = atomicAdd(&g_ctr, 1u);
    __syncthreads();
    if (s_rank != (unsigned int)(gridDim.x - 1)) return;

    __threadfence();                    // acquire: all partials visible
    const int D4 = D >> 2;
    for (int j4 = tid; j4 < D4; j4 += 256) {
        float4 s = make_float4(0.f, 0.f, 0.f, 0.f);
        #pragma unroll 8
        for (int p = 0; p < NT; p++) {
            float4 v = *reinterpret_cast<const float4*>(&g_partM[p][j4 << 2]);
            s.x += v.x; s.y += v.y; s.z += v.z; s.w += v.w;
        }
        s.x *= invD; s.y *= invD; s.z *= invD; s.w *= invD;
        reinterpret_cast<float4*>(g_m)[j4] = s;
    }
    __syncthreads();
    if (tid == 0) g_ctr = 0;            // replay-deterministic reset
}

// ---------------------------------------------------------------------------
// Kernel 2: one block per row, 512 threads.
//   phase 1: row sum of x (block shuffle reduce) -> rowmean
//   phase 2: y[i,j] = kernel[i,j]*m[j];  nk[i,j] = kernel[i,j] + rm*x[i,j]
// Phase-2 x reload hits L1 (8 KB/block).
// ---------------------------------------------------------------------------
__global__ void __launch_bounds__(512) hebb_ew_kernel(
    const float* __restrict__ x, const float* __restrict__ kmat,
    float* __restrict__ y, float* __restrict__ nk,
    int D4, float invD, int write_nk)
{
    __shared__ float wsum[16];

    const int tid = threadIdx.x;
    const size_t base = (size_t)blockIdx.x * D4;

    const float4* x4 = reinterpret_cast<const float4*>(x) + base;
    const float4* k4 = reinterpret_cast<const float4*>(kmat) + base;
    const float4* m4 = reinterpret_cast<const float4*>(g_m);
    float4* y4  = reinterpret_cast<float4*>(y) + base;
    float4* nk4 = reinterpret_cast<float4*>(nk) + base;

    // Phase 1: row sum.
    float s = 0.0f;
    for (int c = tid; c < D4; c += 512) {
        float4 v = x4[c];
        s += (v.x + v.y) + (v.z + v.w);
    }
    #pragma unroll
    for (int o = 16; o > 0; o >>= 1)
        s += __shfl_xor_sync(0xFFFFFFFFu, s, o);
    if ((tid & 31) == 0) wsum[tid >> 5] = s;
    __syncthreads();
    if (tid < 32) {
        float v = (tid < 16) ? wsum[tid] : 0.0f;
        #pragma unroll
        for (int o = 8; o > 0; o >>= 1)
            v += __shfl_xor_sync(0xFFFFFFFFu, v, o);
        if (tid == 0) wsum[0] = v;
    }
    __syncthreads();
    const float rm = wsum[0] * (invD * ETA);

    // Phase 2: outputs.
    for (int c = tid; c < D4; c += 512) {
        float4 kv = k4[c];
        float4 mv = m4[c];
        float4 yv;
        yv.x = kv.x * mv.x;
        yv.y = kv.y * mv.y;
        yv.z = kv.z * mv.z;
        yv.w = kv.w * mv.w;
        y4[c] = yv;
        if (write_nk) {
            float4 xv = x4[c];          // L1 hit
            float4 nv;
            nv.x = fmaf(rm, xv.x, kv.x);
            nv.y = fmaf(rm, xv.y, kv.y);
            nv.z = fmaf(rm, xv.z, kv.z);
            nv.w = fmaf(rm, xv.w, kv.w);
            nk4[c] = nv;
        }
    }
}

extern "C" void kernel_launch(void* const* d_in, const int* in_sizes, int n_in,
                              void* d_out, int out_size)
{
    if (n_in < 2 || !d_in || !d_out || !in_sizes) return;

    const float* x    = (const float*)d_in[0];
    const float* kmat = (const float*)d_in[1];
    float* out        = (float*)d_out;

    const int n = in_sizes[0];           // D*D
    int D = 1;
    while (D < MAXD && D * D < n) D++;   // D = 2048 here
    if (D * D != n || (D % TILE) != 0) return;

    const int NT = D / TILE;              // 32
    const int nPairs = NT * (NT + 1) / 2; // 528
    const int write_nk = (out_size >= 2 * n) ? 1 : 0;
    const float invD = 1.0f / (float)D;

    float* y  = out;
    float* nk = out + n;

    hebb_tile_kernel<<<nPairs, 256>>>(x, D, NT, invD);
    hebb_ew_kernel<<<D, 512>>>(x, kmat, y, nk, D >> 2, invD, write_nk);
}

// round 7
// speedup vs baseline: 1.2836x; 1.2836x over previous
#include <cuda_runtime.h>
#include <math.h>

#define MAXD 2048
#define TILE 64
#define NTMAX (MAXD / TILE)
#define ETA 0.005f

// Disjoint partials: slot [p][j] = contribution of "other tile" p to column/row j.
// Every slot written exactly once per launch -> no zeroing, no accumulate-atomics.
__device__ float g_partM[NTMAX][MAXD];      // 256 KB
__device__ float g_partR[NTMAX][MAXD];      // 256 KB
__device__ float g_m[MAXD];                 // m[j]  (pre-scaled by 1/D)
__device__ float g_rm[MAXD];                // rowmean[b] * ETA / D
__device__ unsigned int g_ctr[NTMAX];       // per-tile arrival counters (self-resetting)

// ---------------------------------------------------------------------------
// Kernel 1: symmetric tile-pair reduction with distributed final reduce.
// Block handles unordered {I,J}, I <= J; reads tiles A = x[I,J], B = x[J,I]
// once, coalesced. P[u,v] = A[u][v]*B[v][u].
//   pass 1: col-sums of P -> partM[I][J*64+v]; row-sums of B -> partR[I][J*64+v]
//   pass 2: row-sums of P -> partM[J][I*64+u]; row-sums of A -> partR[J][I*64+u]
// Tile T receives exactly NT partial writes; the block completing the NT-th
// write reduces tile T's 64 columns into g_m / g_rm (event-driven, no waiting).
// ---------------------------------------------------------------------------
__global__ void __launch_bounds__(256) hebb_tile_kernel(
    const float* __restrict__ x, int D, int NT, float invD)
{
    __shared__ float A[TILE][TILE + 1];
    __shared__ float B[TILE][TILE + 1];
    __shared__ float redM[4][TILE];
    __shared__ float redR[4][TILE];
    __shared__ int doT[2];

    // Invert triangular index: bid -> (I, J), I <= J, row-major upper.
    const int t = blockIdx.x;
    const float fN = 2.0f * (float)NT + 1.0f;
    int I = (int)((fN - sqrtf(fN * fN - 8.0f * (float)t)) * 0.5f);
    #define TRI_BASE(i) ((i) * NT - ((i) * ((i) - 1)) / 2)
    while (I > 0 && TRI_BASE(I) > t) I--;
    while (TRI_BASE(I + 1) <= t) I++;
    const int J = I + (t - TRI_BASE(I));
    #undef TRI_BASE

    const int tid = threadIdx.x;
    const int r   = tid >> 2;          // 0..63  (row within tile)
    const int cg  = (tid & 3) << 4;    // 0,16,32,48 (col group)
    const bool diag = (I == J);

    if (tid == 0) { doT[0] = -1; doT[1] = -1; }

    // Load A (coalesced: warp covers 8 rows x 64 consecutive floats).
    {
        const float* ap = x + (size_t)(I * TILE + r) * D + J * TILE + cg;
        #pragma unroll
        for (int k = 0; k < 16; k += 4) {
            float4 v = *reinterpret_cast<const float4*>(ap + k);
            A[r][cg + k + 0] = v.x; A[r][cg + k + 1] = v.y;
            A[r][cg + k + 2] = v.z; A[r][cg + k + 3] = v.w;
        }
    }
    if (!diag) {
        const float* bp = x + (size_t)(J * TILE + r) * D + I * TILE + cg;
        #pragma unroll
        for (int k = 0; k < 16; k += 4) {
            float4 v = *reinterpret_cast<const float4*>(bp + k);
            B[r][cg + k + 0] = v.x; B[r][cg + k + 1] = v.y;
            B[r][cg + k + 2] = v.z; B[r][cg + k + 3] = v.w;
        }
    }
    __syncthreads();

    float (*Bt)[TILE + 1] = diag ? A : B;

    // Pass 1: per-column v; group g sums rows u0..u0+15.
    {
        const int v  = tid & 63;
        const int g  = tid >> 6;
        const int u0 = g << 4;
        float am = 0.0f, ar = 0.0f;
        #pragma unroll
        for (int k = 0; k < 16; k++) {
            const int u = u0 + k;
            const float bvu = Bt[v][u];   // stride-65 across lanes: conflict-free
            am += A[u][v] * bvu;          // stride-1 across lanes: conflict-free
            ar += bvu;
        }
        redM[g][v] = am;
        redR[g][v] = ar;
    }
    __syncthreads();
    if (tid < 64) {
        g_partM[I][J * TILE + tid] =
            redM[0][tid] + redM[1][tid] + redM[2][tid] + redM[3][tid];
        g_partR[I][J * TILE + tid] =
            redR[0][tid] + redR[1][tid] + redR[2][tid] + redR[3][tid];
    }
    __threadfence();                       // publish partials (release)
    __syncthreads();
    if (tid == 0 && atomicAdd(&g_ctr[J], 1u) == (unsigned)(NT - 1)) doT[0] = J;

    if (!diag) {
        // Pass 2: per-row u; group g sums cols v0..v0+15.
        {
            const int u  = tid & 63;
            const int g  = tid >> 6;
            const int v0 = g << 4;
            float am = 0.0f, ar = 0.0f;
            #pragma unroll
            for (int k = 0; k < 16; k++) {
                const int v = v0 + k;
                const float auv = A[u][v];
                am += auv * B[v][u];
                ar += auv;
            }
            redM[g][u] = am;
            redR[g][u] = ar;
        }
        __syncthreads();
        if (tid < 64) {
            g_partM[J][I * TILE + tid] =
                redM[0][tid] + redM[1][tid] + redM[2][tid] + redM[3][tid];
            g_partR[J][I * TILE + tid] =
                redR[0][tid] + redR[1][tid] + redR[2][tid] + redR[3][tid];
        }
        __threadfence();
        __syncthreads();
        if (tid == 0 && atomicAdd(&g_ctr[I], 1u) == (unsigned)(NT - 1)) doT[1] = I;
    }
    __syncthreads();

    // Event-driven tile reduction (at most 2 tiles; usually 0).
    #pragma unroll
    for (int s = 0; s < 2; s++) {
        const int T = doT[s];
        if (T < 0) continue;
        __threadfence();                   // acquire: all partials for T visible
        const int c = T * TILE + (tid & 63);
        const int g = tid >> 6;
        const int chunk = (NT + 3) >> 2;
        float sm = 0.0f, sr = 0.0f;
        for (int k = 0; k < chunk; k++) {
            const int p = g * chunk + k;
            if (p < NT) { sm += g_partM[p][c]; sr += g_partR[p][c]; }
        }
        redM[g][tid & 63] = sm;
        redR[g][tid & 63] = sr;
        __syncthreads();
        if (tid < 64) {
            const int cc = T * TILE + tid;
            g_m[cc]  = (redM[0][tid] + redM[1][tid] + redM[2][tid] + redM[3][tid]) * invD;
            g_rm[cc] = (redR[0][tid] + redR[1][tid] + redR[2][tid] + redR[3][tid]) * (invD * ETA);
            if (tid == 0) g_ctr[T] = 0;    // replay-deterministic reset
        }
        __syncthreads();
    }
}

// ---------------------------------------------------------------------------
// Kernel 2 (specialized, D compile-time): one block per row, 256 threads,
// thread t handles columns t and t+COLS4/2 (two float4s). No div/mod; rm is a
// single pre-scaled broadcast load; 4 independent LDGs front-batch for MLP.
// ---------------------------------------------------------------------------
template<int COLS4>
__global__ void __launch_bounds__(256) hebb_ew_kernel_s(
    const float* __restrict__ x, const float* __restrict__ kmat,
    float* __restrict__ y, float* __restrict__ nk, int write_nk)
{
    const int tid = threadIdx.x;
    const size_t base = (size_t)blockIdx.x * COLS4;
    const int c0 = tid, c1 = tid + (COLS4 / 2);

    const float4* x4 = reinterpret_cast<const float4*>(x) + base;
    const float4* k4 = reinterpret_cast<const float4*>(kmat) + base;
    const float4* m4 = reinterpret_cast<const float4*>(g_m);
    float4* y4  = reinterpret_cast<float4*>(y) + base;
    float4* nk4 = reinterpret_cast<float4*>(nk) + base;

    const float rm = g_rm[blockIdx.x];     // pre-scaled ETA/D

    float4 ka = k4[c0], kb = k4[c1];
    float4 ma = m4[c0], mb = m4[c1];

    float4 ya, yb;
    ya.x = ka.x * ma.x; ya.y = ka.y * ma.y; ya.z = ka.z * ma.z; ya.w = ka.w * ma.w;
    yb.x = kb.x * mb.x; yb.y = kb.y * mb.y; yb.z = kb.z * mb.z; yb.w = kb.w * mb.w;
    y4[c0] = ya;
    y4[c1] = yb;

    if (write_nk) {
        float4 xa = x4[c0], xb = x4[c1];
        float4 na, nb;
        na.x = fmaf(rm, xa.x, ka.x); na.y = fmaf(rm, xa.y, ka.y);
        na.z = fmaf(rm, xa.z, ka.z); na.w = fmaf(rm, xa.w, ka.w);
        nb.x = fmaf(rm, xb.x, kb.x); nb.y = fmaf(rm, xb.y, kb.y);
        nb.z = fmaf(rm, xb.z, kb.z); nb.w = fmaf(rm, xb.w, kb.w);
        nk4[c0] = na;
        nk4[c1] = nb;
    }
}

// Generic fallback (runtime D4).
__global__ void __launch_bounds__(256) hebb_ew_kernel_g(
    const float* __restrict__ x, const float* __restrict__ kmat,
    float* __restrict__ y, float* __restrict__ nk, int D4, int n4, int write_nk)
{
    int idx = blockIdx.x * 256 + threadIdx.x;
    if (idx >= n4) return;
    const int col4 = idx % D4;
    const int row  = idx / D4;
    float4 kv = reinterpret_cast<const float4*>(kmat)[idx];
    float4 mv = reinterpret_cast<const float4*>(g_m)[col4];
    float4 yv;
    yv.x = kv.x * mv.x; yv.y = kv.y * mv.y; yv.z = kv.z * mv.z; yv.w = kv.w * mv.w;
    reinterpret_cast<float4*>(y)[idx] = yv;
    if (write_nk) {
        float rm = g_rm[row];
        float4 xv = reinterpret_cast<const float4*>(x)[idx];
        float4 nv;
        nv.x = fmaf(rm, xv.x, kv.x); nv.y = fmaf(rm, xv.y, kv.y);
        nv.z = fmaf(rm, xv.z, kv.z); nv.w = fmaf(rm, xv.w, kv.w);
        reinterpret_cast<float4*>(nk)[idx] = nv;
    }
}

extern "C" void kernel_launch(void* const* d_in, const int* in_sizes, int n_in,
                              void* d_out, int out_size)
{
    if (n_in < 2 || !d_in || !d_out || !in_sizes) return;

    const float* x    = (const float*)d_in[0];
    const float* kmat = (const float*)d_in[1];
    float* out        = (float*)d_out;

    const int n = in_sizes[0];           // D*D
    int D = 1;
    while (D < MAXD && D * D < n) D++;   // D = 2048 here
    if (D * D != n || (D % TILE) != 0) return;

    const int NT = D / TILE;              // 32
    const int nPairs = NT * (NT + 1) / 2; // 528
    const int write_nk = (out_size >= 2 * n) ? 1 : 0;
    const float invD = 1.0f / (float)D;

    float* y  = out;
    float* nk = out + n;

    hebb_tile_kernel<<<nPairs, 256>>>(x, D, NT, invD);

    if (D == 2048) {
        hebb_ew_kernel_s<512><<<D, 256>>>(x, kmat, y, nk, write_nk);
    } else {
        const int n4 = n >> 2;
        hebb_ew_kernel_g<<<(n4 + 255) / 256, 256>>>(x, kmat, y, nk, D >> 2, n4, write_nk);
    }
}

// round 8
// speedup vs baseline: 1.3276x; 1.0343x over previous
#include <cuda_runtime.h>
#include <math.h>

#define MAXD 2048
#define TILE 64
#define NTMAX (MAXD / TILE)
#define ETA 0.005f

// Disjoint partials: slot [p][j] = contribution of "other tile" p to column/row j.
// Every slot is written exactly once per launch -> no zeroing, no atomics, no fences.
__device__ float g_partM[NTMAX][MAXD];   // 256 KB
__device__ float g_partR[NTMAX][MAXD];   // 256 KB
__device__ float g_m[MAXD];              // m[j]           (pre-scaled by 1/D)
__device__ float g_rm[MAXD];             // rowmean[b] * ETA / D

// ---------------------------------------------------------------------------
// Kernel 1: symmetric tile-pair reduction -> disjoint partials. Pure compute,
// zero inter-block synchronization.
// Block handles unordered {I,J}, I <= J; reads tiles A = x[I,J], B = x[J,I]
// once, coalesced. P[u,v] = A[u][v]*B[v][u].
//   pass 1: col-sums of P -> partM[I][J*64+v]; row-sums of B -> partR[I][J*64+v]
//   pass 2: row-sums of P -> partM[J][I*64+u]; row-sums of A -> partR[J][I*64+u]
// Diagonal (I==J): pass 1 only, with B := A.
// ---------------------------------------------------------------------------
__global__ void __launch_bounds__(256) hebb_tile_kernel(
    const float* __restrict__ x, int D, int NT)
{
    __shared__ float A[TILE][TILE + 1];
    __shared__ float B[TILE][TILE + 1];
    __shared__ float redM[4][TILE];
    __shared__ float redR[4][TILE];

    // Invert triangular index: bid -> (I, J), I <= J, row-major upper.
    const int t = blockIdx.x;
    const float fN = 2.0f * (float)NT + 1.0f;
    int I = (int)((fN - sqrtf(fN * fN - 8.0f * (float)t)) * 0.5f);
    #define TRI_BASE(i) ((i) * NT - ((i) * ((i) - 1)) / 2)
    while (I > 0 && TRI_BASE(I) > t) I--;
    while (TRI_BASE(I + 1) <= t) I++;
    const int J = I + (t - TRI_BASE(I));
    #undef TRI_BASE

    const int tid = threadIdx.x;
    const int r   = tid >> 2;          // 0..63  (row within tile)
    const int cg  = (tid & 3) << 4;    // 0,16,32,48 (col group)
    const bool diag = (I == J);

    // Load A (coalesced: warp covers 8 rows x 64 consecutive floats).
    {
        const float* ap = x + (size_t)(I * TILE + r) * D + J * TILE + cg;
        #pragma unroll
        for (int k = 0; k < 16; k += 4) {
            float4 v = *reinterpret_cast<const float4*>(ap + k);
            A[r][cg + k + 0] = v.x; A[r][cg + k + 1] = v.y;
            A[r][cg + k + 2] = v.z; A[r][cg + k + 3] = v.w;
        }
    }
    if (!diag) {
        const float* bp = x + (size_t)(J * TILE + r) * D + I * TILE + cg;
        #pragma unroll
        for (int k = 0; k < 16; k += 4) {
            float4 v = *reinterpret_cast<const float4*>(bp + k);
            B[r][cg + k + 0] = v.x; B[r][cg + k + 1] = v.y;
            B[r][cg + k + 2] = v.z; B[r][cg + k + 3] = v.w;
        }
    }
    __syncthreads();

    float (*Bt)[TILE + 1] = diag ? A : B;

    // Pass 1: per-column v; group g sums rows u0..u0+15.
    {
        const int v  = tid & 63;
        const int g  = tid >> 6;
        const int u0 = g << 4;
        float am = 0.0f, ar = 0.0f;
        #pragma unroll
        for (int k = 0; k < 16; k++) {
            const int u = u0 + k;
            const float bvu = Bt[v][u];   // stride-65 across lanes: conflict-free
            am += A[u][v] * bvu;          // stride-1 across lanes: conflict-free
            ar += bvu;
        }
        redM[g][v] = am;
        redR[g][v] = ar;
    }
    __syncthreads();
    if (tid < 64) {
        g_partM[I][J * TILE + tid] =
            redM[0][tid] + redM[1][tid] + redM[2][tid] + redM[3][tid];
        g_partR[I][J * TILE + tid] =
            redR[0][tid] + redR[1][tid] + redR[2][tid] + redR[3][tid];
    }
    if (diag) return;
    __syncthreads();

    // Pass 2: per-row u; group g sums cols v0..v0+15.
    {
        const int u  = tid & 63;
        const int g  = tid >> 6;
        const int v0 = g << 4;
        float am = 0.0f, ar = 0.0f;
        #pragma unroll
        for (int k = 0; k < 16; k++) {
            const int v = v0 + k;
            const float auv = A[u][v];
            am += auv * B[v][u];
            ar += auv;
        }
        redM[g][u] = am;
        redR[g][u] = ar;
    }
    __syncthreads();
    if (tid < 64) {
        g_partM[J][I * TILE + tid] =
            redM[0][tid] + redM[1][tid] + redM[2][tid] + redM[3][tid];
        g_partR[J][I * TILE + tid] =
            redR[0][tid] + redR[1][tid] + redR[2][tid] + redR[3][tid];
    }
}

// ---------------------------------------------------------------------------
// Kernel 2: tiny partials reduction (L2-hot, ~1 MB of reads).
// Thread handles one column j: sums NT partials for M and R, writes
// pre-scaled g_m[j], g_rm[j]. Coalesced across threads.
// ---------------------------------------------------------------------------
__global__ void __launch_bounds__(256) hebb_reduce_kernel(
    int NT, float invD)
{
    const int j = blockIdx.x * 256 + threadIdx.x;
    float sm = 0.0f, sr = 0.0f;
    #pragma unroll 8
    for (int p = 0; p < NT; p++) {
        sm += g_partM[p][j];
        sr += g_partR[p][j];
    }
    g_m[j]  = sm * invD;
    g_rm[j] = sr * (invD * ETA);
}

// ---------------------------------------------------------------------------
// Kernel 3: elementwise outputs; grid = 1024 long-lived blocks, each handles
// rows bid and bid+1024 (independent iterations, no barriers -> row-2 loads
// overlap row-1 stores).
//   y[i,j]  = kernel[i,j] * m[j]
//   nk[i,j] = kernel[i,j] + rm[i] * x[i,j]
// ---------------------------------------------------------------------------
template<int COLS4>
__global__ void __launch_bounds__(256) hebb_ew_kernel_s(
    const float* __restrict__ x, const float* __restrict__ kmat,
    float* __restrict__ y, float* __restrict__ nk, int D, int write_nk)
{
    const int tid = threadIdx.x;
    const int c0 = tid, c1 = tid + 256;
    const float4* m4 = reinterpret_cast<const float4*>(g_m);
    const float4 ma = m4[c0], mb = m4[c1];

    for (int row = blockIdx.x; row < D; row += gridDim.x) {
        const size_t base = (size_t)row * COLS4;
        const float4* x4 = reinterpret_cast<const float4*>(x) + base;
        const float4* k4 = reinterpret_cast<const float4*>(kmat) + base;
        float4* y4  = reinterpret_cast<float4*>(y) + base;
        float4* nk4 = reinterpret_cast<float4*>(nk) + base;

        const float rm = g_rm[row];        // pre-scaled ETA/D
        float4 ka = k4[c0], kb = k4[c1];

        float4 ya, yb;
        ya.x = ka.x * ma.x; ya.y = ka.y * ma.y; ya.z = ka.z * ma.z; ya.w = ka.w * ma.w;
        yb.x = kb.x * mb.x; yb.y = kb.y * mb.y; yb.z = kb.z * mb.z; yb.w = kb.w * mb.w;
        y4[c0] = ya;
        y4[c1] = yb;

        if (write_nk) {
            float4 xa = x4[c0], xb = x4[c1];
            float4 na, nb;
            na.x = fmaf(rm, xa.x, ka.x); na.y = fmaf(rm, xa.y, ka.y);
            na.z = fmaf(rm, xa.z, ka.z); na.w = fmaf(rm, xa.w, ka.w);
            nb.x = fmaf(rm, xb.x, kb.x); nb.y = fmaf(rm, xb.y, kb.y);
            nb.z = fmaf(rm, xb.z, kb.z); nb.w = fmaf(rm, xb.w, kb.w);
            nk4[c0] = na;
            nk4[c1] = nb;
        }
    }
}

// Generic fallback (runtime D4).
__global__ void __launch_bounds__(256) hebb_ew_kernel_g(
    const float* __restrict__ x, const float* __restrict__ kmat,
    float* __restrict__ y, float* __restrict__ nk, int D4, int n4, int write_nk)
{
    int idx = blockIdx.x * 256 + threadIdx.x;
    if (idx >= n4) return;
    const int col4 = idx % D4;
    const int row  = idx / D4;
    float4 kv = reinterpret_cast<const float4*>(kmat)[idx];
    float4 mv = reinterpret_cast<const float4*>(g_m)[col4];
    float4 yv;
    yv.x = kv.x * mv.x; yv.y = kv.y * mv.y; yv.z = kv.z * mv.z; yv.w = kv.w * mv.w;
    reinterpret_cast<float4*>(y)[idx] = yv;
    if (write_nk) {
        float rm = g_rm[row];
        float4 xv = reinterpret_cast<const float4*>(x)[idx];
        float4 nv;
        nv.x = fmaf(rm, xv.x, kv.x); nv.y = fmaf(rm, xv.y, kv.y);
        nv.z = fmaf(rm, xv.z, kv.z); nv.w = fmaf(rm, xv.w, kv.w);
        reinterpret_cast<float4*>(nk)[idx] = nv;
    }
}

extern "C" void kernel_launch(void* const* d_in, const int* in_sizes, int n_in,
                              void* d_out, int out_size)
{
    if (n_in < 2 || !d_in || !d_out || !in_sizes) return;

    const float* x    = (const float*)d_in[0];
    const float* kmat = (const float*)d_in[1];
    float* out        = (float*)d_out;

    const int n = in_sizes[0];           // D*D
    int D = 1;
    while (D < MAXD && D * D < n) D++;   // D = 2048 here
    if (D * D != n || (D % TILE) != 0) return;

    const int NT = D / TILE;              // 32
    const int nPairs = NT * (NT + 1) / 2; // 528
    const int write_nk = (out_size >= 2 * n) ? 1 : 0;
    const float invD = 1.0f / (float)D;

    float* y  = out;
    float* nk = out + n;

    hebb_tile_kernel<<<nPairs, 256>>>(x, D, NT);
    hebb_reduce_kernel<<<D / 256, 256>>>(NT, invD);

    if (D == 2048) {
        hebb_ew_kernel_s<512><<<1024, 256>>>(x, kmat, y, nk, D, write_nk);
    } else {
        const int n4 = n >> 2;
        hebb_ew_kernel_g<<<(n4 + 255) / 256, 256>>>(x, kmat, y, nk, D >> 2, n4, write_nk);
    }
}

// round 9
// speedup vs baseline: 1.4774x; 1.1128x over previous
#include <cuda_runtime.h>
#include <math.h>

#define MAXD 2048
#define TILE 32
#define NTMAX (MAXD / TILE)     // 64
#define ETA 0.005f

// Disjoint partials: slot [p][j] = contribution of column-tile p to column/row j.
// Every slot is written exactly once per launch -> no zeroing, no atomics, no fences.
__device__ float g_partM[NTMAX][MAXD];   // 512 KB
__device__ float g_partR[NTMAX][MAXD];   // 512 KB
__device__ float g_m[MAXD];              // m[j]           (pre-scaled by 1/D)
__device__ float g_rm[MAXD];             // rowmean[b] * ETA / D

// ---------------------------------------------------------------------------
// Kernel 1: symmetric tile-pair reduction -> disjoint partials.
// TILE=32 => 2080 blocks, 10.5 KB smem: 8 blocks/SM, latency well hidden.
// Block {I,J}, I<=J: A = x[I,J], B = x[J,I], read once, coalesced.
//   pass 1: partM[I][J*32+v] = sum_u A[u][v]*B[v][u];  partR[I][J*32+v] = sum_u B[v][u]
//   pass 2: partM[J][I*32+u] = sum_v A[u][v]*B[v][u];  partR[J][I*32+u] = sum_v A[u][v]
// Diagonal (I==J): pass 1 only with B := A.
// ---------------------------------------------------------------------------
__global__ void __launch_bounds__(256) hebb_tile_kernel(
    const float* __restrict__ x, int D, int NT)
{
    __shared__ float A[TILE][TILE + 1];
    __shared__ float B[TILE][TILE + 1];
    __shared__ float redM[8][TILE];
    __shared__ float redR[8][TILE];

    // Invert triangular index: bid -> (I, J), I <= J, row-major upper.
    const int t = blockIdx.x;
    const float fN = 2.0f * (float)NT + 1.0f;
    int I = (int)((fN - sqrtf(fN * fN - 8.0f * (float)t)) * 0.5f);
    #define TRI_BASE(i) ((i) * NT - ((i) * ((i) - 1)) / 2)
    while (I > 0 && TRI_BASE(I) > t) I--;
    while (TRI_BASE(I + 1) <= t) I++;
    const int J = I + (t - TRI_BASE(I));
    #undef TRI_BASE

    const int tid = threadIdx.x;
    const int r   = tid >> 3;          // 0..31 (row within tile)
    const int c   = (tid & 7) << 2;    // 0,4,...,28 (float4 col)
    const bool diag = (I == J);

    // Load A (one float4 per thread; warp = 4 rows x 128B -> coalesced).
    {
        float4 v = *reinterpret_cast<const float4*>(
            x + (size_t)(I * TILE + r) * D + J * TILE + c);
        A[r][c + 0] = v.x; A[r][c + 1] = v.y; A[r][c + 2] = v.z; A[r][c + 3] = v.w;
    }
    if (!diag) {
        float4 v = *reinterpret_cast<const float4*>(
            x + (size_t)(J * TILE + r) * D + I * TILE + c);
        B[r][c + 0] = v.x; B[r][c + 1] = v.y; B[r][c + 2] = v.z; B[r][c + 3] = v.w;
    }
    __syncthreads();

    float (*Bt)[TILE + 1] = diag ? A : B;

    // Pass 1: per-column v; group g (0..7) sums rows u = 4g..4g+3.
    {
        const int v  = tid & 31;
        const int g  = tid >> 5;
        const int u0 = g << 2;
        float am = 0.0f, ar = 0.0f;
        #pragma unroll
        for (int k = 0; k < 4; k++) {
            const int u = u0 + k;
            const float bvu = Bt[v][u];   // stride-33 across lanes: conflict-free
            am += A[u][v] * bvu;          // stride-1  across lanes: conflict-free
            ar += bvu;
        }
        redM[g][v] = am;
        redR[g][v] = ar;
    }
    __syncthreads();
    if (tid < 32) {
        float sm = 0.0f, sr = 0.0f;
        #pragma unroll
        for (int g = 0; g < 8; g++) { sm += redM[g][tid]; sr += redR[g][tid]; }
        g_partM[I][J * TILE + tid] = sm;
        g_partR[I][J * TILE + tid] = sr;
    }
    if (diag) return;
    __syncthreads();

    // Pass 2: per-row u; group g sums cols v = 4g..4g+3.
    {
        const int u  = tid & 31;
        const int g  = tid >> 5;
        const int v0 = g << 2;
        float am = 0.0f, ar = 0.0f;
        #pragma unroll
        for (int k = 0; k < 4; k++) {
            const int v = v0 + k;
            const float auv = A[u][v];    // stride-33 across lanes: conflict-free
            am += auv * B[v][u];          // stride-1  across lanes: conflict-free
            ar += auv;
        }
        redM[g][u] = am;
        redR[g][u] = ar;
    }
    __syncthreads();
    if (tid < 32) {
        float sm = 0.0f, sr = 0.0f;
        #pragma unroll
        for (int g = 0; g < 8; g++) { sm += redM[g][tid]; sr += redR[g][tid]; }
        g_partM[J][I * TILE + tid] = sm;
        g_partR[J][I * TILE + tid] = sr;
    }
}

// ---------------------------------------------------------------------------
// Kernel 2: partials reduction, parallel over columns AND p.
// Block = 32 columns x 8 p-groups; ~1 MB of L2-hot reads across 64 blocks.
// ---------------------------------------------------------------------------
__global__ void __launch_bounds__(256) hebb_reduce_kernel(int NT, float invD)
{
    __shared__ float sM[8][33];
    __shared__ float sR[8][33];
    const int lane = threadIdx.x & 31;
    const int g    = threadIdx.x >> 5;
    const int j    = blockIdx.x * 32 + lane;

    float sm = 0.0f, sr = 0.0f;
    for (int p = g; p < NT; p += 8) {
        sm += g_partM[p][j];
        sr += g_partR[p][j];
    }
    sM[g][lane] = sm;
    sR[g][lane] = sr;
    __syncthreads();
    if (threadIdx.x < 32) {
        float m = 0.0f, r = 0.0f;
        #pragma unroll
        for (int k = 0; k < 8; k++) { m += sM[k][threadIdx.x]; r += sR[k][threadIdx.x]; }
        const int jj = blockIdx.x * 32 + threadIdx.x;
        g_m[jj]  = m * invD;
        g_rm[jj] = r * (invD * ETA);
    }
}

// ---------------------------------------------------------------------------
// Kernel 3: elementwise outputs. 1024 blocks, each handles rows 2*bid, 2*bid+1
// with ALL loads front-batched (10 LDG.128 per thread in flight).
//   y[i,j]  = kernel[i,j] * m[j]
//   nk[i,j] = kernel[i,j] + rm[i] * x[i,j]
// ---------------------------------------------------------------------------
template<int COLS4, bool NK>
__global__ void __launch_bounds__(256) hebb_ew_kernel_s(
    const float* __restrict__ x, const float* __restrict__ kmat,
    float* __restrict__ y, float* __restrict__ nk)
{
    const int tid = threadIdx.x;
    const int c0 = tid, c1 = tid + 256;
    const int row = blockIdx.x * 2;
    const size_t b0 = (size_t)row * COLS4;
    const size_t b1 = b0 + COLS4;

    const float4* m4 = reinterpret_cast<const float4*>(g_m);
    const float4* k0 = reinterpret_cast<const float4*>(kmat) + b0;
    const float4* k1 = reinterpret_cast<const float4*>(kmat) + b1;
    const float4* x0 = reinterpret_cast<const float4*>(x) + b0;
    const float4* x1 = reinterpret_cast<const float4*>(x) + b1;

    // Front-batched loads (independent -> max MLP).
    float4 ma = m4[c0], mb = m4[c1];
    float4 ka0 = k0[c0], kb0 = k0[c1];
    float4 ka1 = k1[c0], kb1 = k1[c1];
    float4 xa0, xb0, xa1, xb1;
    if (NK) { xa0 = x0[c0]; xb0 = x0[c1]; xa1 = x1[c0]; xb1 = x1[c1]; }
    const float rm0 = g_rm[row];
    const float rm1 = g_rm[row + 1];

    float4* y0 = reinterpret_cast<float4*>(y) + b0;
    float4* y1 = reinterpret_cast<float4*>(y) + b1;

    float4 v;
    v.x = ka0.x * ma.x; v.y = ka0.y * ma.y; v.z = ka0.z * ma.z; v.w = ka0.w * ma.w;
    y0[c0] = v;
    v.x = kb0.x * mb.x; v.y = kb0.y * mb.y; v.z = kb0.z * mb.z; v.w = kb0.w * mb.w;
    y0[c1] = v;
    v.x = ka1.x * ma.x; v.y = ka1.y * ma.y; v.z = ka1.z * ma.z; v.w = ka1.w * ma.w;
    y1[c0] = v;
    v.x = kb1.x * mb.x; v.y = kb1.y * mb.y; v.z = kb1.z * mb.z; v.w = kb1.w * mb.w;
    y1[c1] = v;

    if (NK) {
        float4* n0 = reinterpret_cast<float4*>(nk) + b0;
        float4* n1 = reinterpret_cast<float4*>(nk) + b1;
        v.x = fmaf(rm0, xa0.x, ka0.x); v.y = fmaf(rm0, xa0.y, ka0.y);
        v.z = fmaf(rm0, xa0.z, ka0.z); v.w = fmaf(rm0, xa0.w, ka0.w);
        n0[c0] = v;
        v.x = fmaf(rm0, xb0.x, kb0.x); v.y = fmaf(rm0, xb0.y, kb0.y);
        v.z = fmaf(rm0, xb0.z, kb0.z); v.w = fmaf(rm0, xb0.w, kb0.w);
        n0[c1] = v;
        v.x = fmaf(rm1, xa1.x, ka1.x); v.y = fmaf(rm1, xa1.y, ka1.y);
        v.z = fmaf(rm1, xa1.z, ka1.z); v.w = fmaf(rm1, xa1.w, ka1.w);
        n1[c0] = v;
        v.x = fmaf(rm1, xb1.x, kb1.x); v.y = fmaf(rm1, xb1.y, kb1.y);
        v.z = fmaf(rm1, xb1.z, kb1.z); v.w = fmaf(rm1, xb1.w, kb1.w);
        n1[c1] = v;
    }
}

// Generic fallback (runtime D4).
__global__ void __launch_bounds__(256) hebb_ew_kernel_g(
    const float* __restrict__ x, const float* __restrict__ kmat,
    float* __restrict__ y, float* __restrict__ nk, int D4, int n4, int write_nk)
{
    int idx = blockIdx.x * 256 + threadIdx.x;
    if (idx >= n4) return;
    const int col4 = idx % D4;
    const int row  = idx / D4;
    float4 kv = reinterpret_cast<const float4*>(kmat)[idx];
    float4 mv = reinterpret_cast<const float4*>(g_m)[col4];
    float4 yv;
    yv.x = kv.x * mv.x; yv.y = kv.y * mv.y; yv.z = kv.z * mv.z; yv.w = kv.w * mv.w;
    reinterpret_cast<float4*>(y)[idx] = yv;
    if (write_nk) {
        float rm = g_rm[row];
        float4 xv = reinterpret_cast<const float4*>(x)[idx];
        float4 nv;
        nv.x = fmaf(rm, xv.x, kv.x); nv.y = fmaf(rm, xv.y, kv.y);
        nv.z = fmaf(rm, xv.z, kv.z); nv.w = fmaf(rm, xv.w, kv.w);
        reinterpret_cast<float4*>(nk)[idx] = nv;
    }
}

extern "C" void kernel_launch(void* const* d_in, const int* in_sizes, int n_in,
                              void* d_out, int out_size)
{
    if (n_in < 2 || !d_in || !d_out || !in_sizes) return;

    const float* x    = (const float*)d_in[0];
    const float* kmat = (const float*)d_in[1];
    float* out        = (float*)d_out;

    const int n = in_sizes[0];           // D*D
    int D = 1;
    while (D < MAXD && D * D < n) D++;   // D = 2048 here
    if (D * D != n || (D % TILE) != 0) return;

    const int NT = D / TILE;              // 64
    const int nPairs = NT * (NT + 1) / 2; // 2080
    const int write_nk = (out_size >= 2 * n) ? 1 : 0;
    const float invD = 1.0f / (float)D;

    float* y  = out;
    float* nk = out + n;

    hebb_tile_kernel<<<nPairs, 256>>>(x, D, NT);
    hebb_reduce_kernel<<<D / 32, 256>>>(NT, invD);

    if (D == 2048) {
        if (write_nk)
            hebb_ew_kernel_s<512, true><<<1024, 256>>>(x, kmat, y, nk);
        else
            hebb_ew_kernel_s<512, false><<<1024, 256>>>(x, kmat, y, nk);
    } else {
        const int n4 = n >> 2;
        hebb_ew_kernel_g<<<(n4 + 255) / 256, 256>>>(x, kmat, y, nk, D >> 2, n4, write_nk);
    }
}